// round 1
// baseline (speedup 1.0000x reference)
#include <cuda_runtime.h>

// ---------------------------------------------------------------------------
// MultiSegmentLoss fused kernel.
// Inputs (metadata order):
//   0 loc_data       (B,K,2) f32
//   1 conf_data      (B,K,2) f32
//   2 prop_loc_data  (B,K,2) f32
//   3 prop_conf_data (B,K,2) f32
//   4 center_data    (B,K,1) f32
//   5 priors         (K,1)   f32
//   6 targets        (B,N,3) f32   [t0, t1, label]
// Output: 5 f32 scalars.
// ---------------------------------------------------------------------------

#define MAXPART 8192

__device__ float g_part[MAXPART * 8];

__global__ __launch_bounds__(256) void msl_main(
    const float* __restrict__ loc,
    const float* __restrict__ conf_d,
    const float* __restrict__ ploc,
    const float* __restrict__ pconf_d,
    const float* __restrict__ center,
    const float* __restrict__ priors,
    const float* __restrict__ targets,
    int K, int N)
{
    extern __shared__ float sh[];
    float2* sp   = reinterpret_cast<float2*>(sh);  // N pairs of (t0*256, t1*256)
    float*  slab = sh + 2 * N;                     // N labels
    const int b = blockIdx.y;
    const float* tg = targets + (size_t)b * N * 3;
    for (int i = threadIdx.x; i < N; i += blockDim.x) {
        float t0 = tg[i * 3 + 0];
        float t1 = tg[i * 3 + 1];
        sp[i]   = make_float2(t0 * 256.0f, t1 * 256.0f);
        slab[i] = tg[i * 3 + 2];
    }
    __syncthreads();

    const float EPS = 1.1920929e-7f;   // jnp.finfo(float32).eps
    float a0 = 0.f, a1 = 0.f, a2 = 0.f, a3 = 0.f, a4 = 0.f, a5 = 0.f, a6 = 0.f;
    const size_t base = (size_t)b * (size_t)K;
    const int stride = gridDim.x * blockDim.x;

    for (int k = blockIdx.x * blockDim.x + threadIdx.x; k < K; k += stride) {
        // NOTE: (c - t0)*256 == c*256 - t0*256 bit-exactly (pow2 scaling
        // commutes with fp rounding), so pre-scaled truths are safe.
        const float c256 = priors[k] * 256.0f;

        float best = 3.402823466e38f;
        int   bi   = 0;
        #pragma unroll 4
        for (int n = 0; n < N; n++) {
            float2 t = sp[n];
            float l = c256 - t.x;
            float r = t.y - c256;
            float area = (fminf(l, r) < 0.0f) ? 512.0f : (l + r);
            bool upd = area < best;          // strict < : first-min (argmin) semantics
            best = upd ? area : best;
            bi   = upd ? n    : bi;
        }

        float2 tb  = sp[bi];
        float  ltl = c256 - tb.x;            // loc_t left
        float  ltr = tb.y - c256;            // loc_t right
        int confi  = (best >= 512.0f) ? 0 : (int)slab[bi];

        float2 pre = reinterpret_cast<const float2*>(loc)[base + k];
        float pl = pre.x, pr = pre.y;

        // iou(pre_loc, loc_t)
        float inter = fminf(pl, ltl) + fminf(pr, ltr);
        float uni   = pl + pr + ltl + ltr - inter;
        float iou   = inter / fmaxf(uni, EPS);
        int   pconfi = (iou < 0.5f) ? 0 : confi;
        float posf = (confi  > 0) ? 1.0f : 0.0f;
        float ppf  = (pconfi > 0) ? 1.0f : 0.0f;

        // GIoU loss (pred = loc_data, target = loc_t)
        float ac   = fmaxf(pl, ltl) + fmaxf(pr, ltr);
        float giou = iou - (ac - uni) / fmaxf(ac, EPS);
        a0 += (1.0f - giou) * posf;

        // prop-loc L1
        float2 pld = reinterpret_cast<const float2*>(ploc)[base + k];
        float hw = 0.5f * (pl + pr);
        float plt0 = (ltl - pl) / hw;
        float plt1 = (ltr - pr) / hw;
        a2 += (fabsf(pld.x - plt0) + fabsf(pld.y - plt1)) * ppf;

        // centerness BCE vs clipped iou of refined location
        float cl0 = hw * pld.x + pl;
        float cl1 = hw * pld.y + pr;
        float in2  = fminf(cl0, ltl) + fminf(cl1, ltr);
        float un2  = cl0 + cl1 + ltl + ltr - in2;
        float iou2 = fmaxf(in2 / fmaxf(un2, EPS), 0.0f);
        float lg   = center[base + k];
        float bce  = fmaxf(lg, 0.0f) - lg * iou2 + log1pf(expf(-fabsf(lg)));
        a4 += bce * posf;

        // focal(conf_data, conf_t):  pt = softmax[target] = sigmoid(c_t - c_other)
        float2 cd = reinterpret_cast<const float2*>(conf_d)[base + k];
        {
            float d  = (confi != 0) ? (cd.x - cd.y) : (cd.y - cd.x);
            float pt = 1.0f / (1.0f + expf(d)) + 1e-6f;
            float al = (confi != 0) ? 0.75f : 0.25f;
            float om = 1.0f - pt;
            a1 -= om * om * al * logf(pt);
        }
        // focal(prop_conf_data, prop_conf_t)
        float2 pcd = reinterpret_cast<const float2*>(pconf_d)[base + k];
        {
            float d  = (pconfi != 0) ? (pcd.x - pcd.y) : (pcd.y - pcd.x);
            float pt = 1.0f / (1.0f + expf(d)) + 1e-6f;
            float al = (pconfi != 0) ? 0.75f : 0.25f;
            float om = 1.0f - pt;
            a3 -= om * om * al * logf(pt);
        }
        a5 += posf;
        a6 += ppf;
    }

    // warp reduction
    #pragma unroll
    for (int off = 16; off; off >>= 1) {
        a0 += __shfl_down_sync(0xffffffffu, a0, off);
        a1 += __shfl_down_sync(0xffffffffu, a1, off);
        a2 += __shfl_down_sync(0xffffffffu, a2, off);
        a3 += __shfl_down_sync(0xffffffffu, a3, off);
        a4 += __shfl_down_sync(0xffffffffu, a4, off);
        a5 += __shfl_down_sync(0xffffffffu, a5, off);
        a6 += __shfl_down_sync(0xffffffffu, a6, off);
    }
    __shared__ float red[8][8];
    int w  = threadIdx.x >> 5;
    int ln = threadIdx.x & 31;
    if (ln == 0) {
        red[w][0] = a0; red[w][1] = a1; red[w][2] = a2; red[w][3] = a3;
        red[w][4] = a4; red[w][5] = a5; red[w][6] = a6;
    }
    __syncthreads();
    if (threadIdx.x < 7) {
        float s = 0.0f;
        #pragma unroll
        for (int i = 0; i < 8; i++) s += red[i][threadIdx.x];
        int blk = blockIdx.y * gridDim.x + blockIdx.x;
        g_part[blk * 8 + threadIdx.x] = s;   // deterministic per-block slot (no atomics)
    }
}

__global__ void msl_finalize(float* __restrict__ out, int nblk, int out_size)
{
    __shared__ float tot[7];
    int w  = threadIdx.x >> 5;   // 7 warps used, one per accumulator
    int ln = threadIdx.x & 31;
    if (w < 7) {
        float s = 0.0f;
        for (int i = ln; i < nblk; i += 32) s += g_part[i * 8 + w];
        #pragma unroll
        for (int off = 16; off; off >>= 1) s += __shfl_down_sync(0xffffffffu, s, off);
        if (ln == 0) tot[w] = s;
    }
    __syncthreads();
    if (threadIdx.x == 0) {
        float np = fmaxf(tot[5], 1.0f);
        float pn = fmaxf(tot[6], 1.0f);
        float r0 = tot[0] / np;   // loss_l / Np
        float r1 = tot[1] / np;   // loss_c / Np
        float r2 = tot[2] / pn;   // loss_prop_l / PN
        float r3 = tot[3] / pn;   // loss_prop_c / PN
        float r4 = tot[4] / np;   // loss_ct / Np
        if (out_size > 0) out[0] = r0;
        if (out_size > 1) out[1] = r1;
        if (out_size > 2) out[2] = r2;
        if (out_size > 3) out[3] = r3;
        if (out_size > 4) out[4] = r4;
    }
}

extern "C" void kernel_launch(void* const* d_in, const int* in_sizes, int n_in,
                              void* d_out, int out_size)
{
    const float* loc     = (const float*)d_in[0];
    const float* conf    = (const float*)d_in[1];
    const float* ploc    = (const float*)d_in[2];
    const float* pconf   = (const float*)d_in[3];
    const float* center  = (const float*)d_in[4];
    const float* priors  = (const float*)d_in[5];
    const float* targets = (const float*)d_in[6];

    int K = in_sizes[5];                 // priors: (K,1)
    int B = in_sizes[4] / K;             // center: (B,K,1)
    int N = in_sizes[6] / (B * 3);       // targets: (B,N,3)

    int gx = 74;                          // 74*16 = 1184 blocks (~8/SM)
    while ((long)gx * B > MAXPART && gx > 1) gx /= 2;

    dim3 grid(gx, B);
    size_t shmem = (size_t)3 * N * sizeof(float);
    msl_main<<<grid, 256, shmem>>>(loc, conf, ploc, pconf, center, priors,
                                   targets, K, N);
    msl_finalize<<<1, 256>>>((float*)d_out, gx * B, out_size);
}

// round 2
// speedup vs baseline: 1.7447x; 1.7447x over previous
#include <cuda_runtime.h>

// ---------------------------------------------------------------------------
// MultiSegmentLoss fused kernel (single launch, last-block finalize).
// Inputs (metadata order):
//   0 loc_data       (B,K,2) f32
//   1 conf_data      (B,K,2) f32
//   2 prop_loc_data  (B,K,2) f32
//   3 prop_conf_data (B,K,2) f32
//   4 center_data    (B,K,1) f32
//   5 priors         (K,1)   f32
//   6 targets        (B,N,3) f32   [t0, t1, label]
// Output: 5 f32 scalars.
//
// Matching trick: area(l+r) == (t1-t0)*256 independent of the prior center,
// and every valid area < 256 < maxn=512.  Hence argmin == the smallest-width
// truth containing the center.  Truths are rank-sorted by width once per
// block; per prior we early-exit on the first containing interval.
// ---------------------------------------------------------------------------

#define MAXPART 8192

__device__ float        g_part[MAXPART * 8];
__device__ unsigned int g_count = 0;

__global__ __launch_bounds__(256) void msl_main(
    const float* __restrict__ loc,
    const float* __restrict__ conf_d,
    const float* __restrict__ ploc,
    const float* __restrict__ pconf_d,
    const float* __restrict__ center,
    const float* __restrict__ priors,
    const float* __restrict__ targets,
    int K, int N, int nblk,
    float* __restrict__ out, int out_size)
{
    // shared layout: [sorted float2 xN][raw float2 xN][sorted label xN][raw label xN]
    extern __shared__ float sh[];
    float2* sp     = reinterpret_cast<float2*>(sh);            // sorted (t0*256,t1*256)
    float2* raw    = reinterpret_cast<float2*>(sh) + N;        // unsorted
    float*  slab   = sh + 4 * N;                               // sorted labels
    float*  rawlab = sh + 5 * N;

    const int b = blockIdx.y;
    const float* tg = targets + (size_t)b * N * 3;
    if (threadIdx.x < N) {
        int i = threadIdx.x;
        float t0 = tg[i * 3 + 0] * 256.0f;
        float t1 = tg[i * 3 + 1] * 256.0f;
        raw[i]    = make_float2(t0, t1);
        rawlab[i] = tg[i * 3 + 2];
    }
    __syncthreads();
    if (threadIdx.x < N) {
        int i = threadIdx.x;
        float2 ti = raw[i];
        float  wi = ti.y - ti.x;
        int rank = 0;
        for (int j = 0; j < N; j++) {
            float2 tj = raw[j];
            float  wj = tj.y - tj.x;
            rank += (wj < wi) || (wj == wi && j < i);   // stable: ties keep orig order
        }
        sp[rank]   = ti;
        slab[rank] = rawlab[i];
    }
    __syncthreads();

    const float EPS = 1.1920929e-7f;   // jnp.finfo(float32).eps
    float a0 = 0.f, a1 = 0.f, a2 = 0.f, a3 = 0.f, a4 = 0.f, a5 = 0.f, a6 = 0.f;
    const size_t base = (size_t)b * (size_t)K;
    const int stride = gridDim.x * blockDim.x;

    for (int k = blockIdx.x * blockDim.x + threadIdx.x; k < K; k += stride) {
        // Hoisted global loads: overlap their latency with the search loop.
        const float  c256 = priors[k] * 256.0f;
        const float2 pre  = __ldcs(reinterpret_cast<const float2*>(loc)     + base + k);
        const float2 pld  = __ldcs(reinterpret_cast<const float2*>(ploc)    + base + k);
        const float2 cd   = __ldcs(reinterpret_cast<const float2*>(conf_d)  + base + k);
        const float2 pcd  = __ldcs(reinterpret_cast<const float2*>(pconf_d) + base + k);
        const float  lg   = __ldcs(center + base + k);

        // First containing interval in width-sorted order == argmin of area.
        int bi = -1;
        #pragma unroll 1
        for (int n = 0; n < N; n++) {
            float2 t = sp[n];
            if (c256 >= t.x && c256 <= t.y) { bi = n; break; }
        }
        const bool found = (bi >= 0);
        const int  si    = found ? bi : 0;   // no-hit: value fully gated, any idx ok
        float2 tb  = sp[si];
        int confi  = found ? (int)slab[si] : 0;

        float ltl = c256 - tb.x;             // loc_t left
        float ltr = tb.y - c256;             // loc_t right
        float pl = pre.x, pr = pre.y;

        // iou(pre_loc, loc_t)
        float inter = fminf(pl, ltl) + fminf(pr, ltr);
        float uni   = pl + pr + ltl + ltr - inter;
        float iou   = inter / fmaxf(uni, EPS);
        int   pconfi = (iou < 0.5f) ? 0 : confi;
        float posf = (confi  > 0) ? 1.0f : 0.0f;
        float ppf  = (pconfi > 0) ? 1.0f : 0.0f;

        // GIoU loss
        float ac   = fmaxf(pl, ltl) + fmaxf(pr, ltr);
        float giou = iou - (ac - uni) / fmaxf(ac, EPS);
        a0 += (1.0f - giou) * posf;

        // prop-loc L1
        float hw = 0.5f * (pl + pr);
        float plt0 = (ltl - pl) / hw;
        float plt1 = (ltr - pr) / hw;
        a2 += (fabsf(pld.x - plt0) + fabsf(pld.y - plt1)) * ppf;

        // centerness BCE vs clipped iou of refined location
        float cl0 = hw * pld.x + pl;
        float cl1 = hw * pld.y + pr;
        float in2  = fminf(cl0, ltl) + fminf(cl1, ltr);
        float un2  = cl0 + cl1 + ltl + ltr - in2;
        float iou2 = fmaxf(in2 / fmaxf(un2, EPS), 0.0f);
        float bce  = fmaxf(lg, 0.0f) - lg * iou2 + log1pf(expf(-fabsf(lg)));
        a4 += bce * posf;

        // focal(conf_data, conf_t):  pt = softmax[target] = sigmoid(c_t - c_other)
        {
            float d  = (confi != 0) ? (cd.x - cd.y) : (cd.y - cd.x);
            float pt = 1.0f / (1.0f + expf(d)) + 1e-6f;
            float al = (confi != 0) ? 0.75f : 0.25f;
            float om = 1.0f - pt;
            a1 -= om * om * al * logf(pt);
        }
        // focal(prop_conf_data, prop_conf_t)
        {
            float d  = (pconfi != 0) ? (pcd.x - pcd.y) : (pcd.y - pcd.x);
            float pt = 1.0f / (1.0f + expf(d)) + 1e-6f;
            float al = (pconfi != 0) ? 0.75f : 0.25f;
            float om = 1.0f - pt;
            a3 -= om * om * al * logf(pt);
        }
        a5 += posf;
        a6 += ppf;
    }

    // warp reduction
    #pragma unroll
    for (int off = 16; off; off >>= 1) {
        a0 += __shfl_down_sync(0xffffffffu, a0, off);
        a1 += __shfl_down_sync(0xffffffffu, a1, off);
        a2 += __shfl_down_sync(0xffffffffu, a2, off);
        a3 += __shfl_down_sync(0xffffffffu, a3, off);
        a4 += __shfl_down_sync(0xffffffffu, a4, off);
        a5 += __shfl_down_sync(0xffffffffu, a5, off);
        a6 += __shfl_down_sync(0xffffffffu, a6, off);
    }
    __shared__ float red[8][8];
    int w  = threadIdx.x >> 5;
    int ln = threadIdx.x & 31;
    if (ln == 0) {
        red[w][0] = a0; red[w][1] = a1; red[w][2] = a2; red[w][3] = a3;
        red[w][4] = a4; red[w][5] = a5; red[w][6] = a6;
    }
    __syncthreads();
    const int blk = blockIdx.y * gridDim.x + blockIdx.x;
    if (threadIdx.x < 7) {
        float s = 0.0f;
        #pragma unroll
        for (int i = 0; i < 8; i++) s += red[i][threadIdx.x];
        g_part[blk * 8 + threadIdx.x] = s;   // deterministic per-block slot
        __threadfence();
    }
    __syncthreads();

    // ---- last-block finalize (deterministic fixed-order sum) ----
    __shared__ unsigned int s_ticket;
    if (threadIdx.x == 0) s_ticket = atomicAdd(&g_count, 1u);
    __syncthreads();
    if (s_ticket == (unsigned)(nblk - 1)) {
        __shared__ float tot[7];
        float s = 0.0f;
        if (w < 7) {
            for (int i = ln; i < nblk; i += 32) s += g_part[i * 8 + w];
            #pragma unroll
            for (int off = 16; off; off >>= 1) s += __shfl_down_sync(0xffffffffu, s, off);
            if (ln == 0) tot[w] = s;
        }
        __syncthreads();
        if (threadIdx.x == 0) {
            g_count = 0;                       // self-reset for graph replay
            float np = fmaxf(tot[5], 1.0f);
            float pn = fmaxf(tot[6], 1.0f);
            if (out_size > 0) out[0] = tot[0] / np;   // loss_l / Np
            if (out_size > 1) out[1] = tot[1] / np;   // loss_c / Np
            if (out_size > 2) out[2] = tot[2] / pn;   // loss_prop_l / PN
            if (out_size > 3) out[3] = tot[3] / pn;   // loss_prop_c / PN
            if (out_size > 4) out[4] = tot[4] / np;   // loss_ct / Np
        }
    }
}

extern "C" void kernel_launch(void* const* d_in, const int* in_sizes, int n_in,
                              void* d_out, int out_size)
{
    const float* loc     = (const float*)d_in[0];
    const float* conf    = (const float*)d_in[1];
    const float* ploc    = (const float*)d_in[2];
    const float* pconf   = (const float*)d_in[3];
    const float* center  = (const float*)d_in[4];
    const float* priors  = (const float*)d_in[5];
    const float* targets = (const float*)d_in[6];

    int K = in_sizes[5];                 // priors: (K,1)
    int B = in_sizes[4] / K;             // center: (B,K,1)
    int N = in_sizes[6] / (B * 3);       // targets: (B,N,3)

    int gx = 74;                          // 74*16 = 1184 blocks (~8/SM)
    while ((long)gx * B > MAXPART && gx > 1) gx /= 2;
    int nblk = gx * B;

    dim3 grid(gx, B);
    size_t shmem = (size_t)6 * N * sizeof(float);
    msl_main<<<grid, 256, shmem>>>(loc, conf, ploc, pconf, center, priors,
                                   targets, K, N, nblk, (float*)d_out, out_size);
}

// round 3
// speedup vs baseline: 2.2905x; 1.3128x over previous
#include <cuda_runtime.h>

// ---------------------------------------------------------------------------
// MultiSegmentLoss fused kernel (single launch, last-block finalize).
// Match = first containing interval in width-sorted order (== argmin area).
// That answer is piecewise-constant in the prior center with breakpoints at
// the 2N interval endpoints -> precompute per-segment answers once per block,
// then each prior does a 7-step branchless binary search.
// ---------------------------------------------------------------------------

#define MAXPART 8192

__device__ float        g_part[MAXPART * 8];
__device__ unsigned int g_count = 0;

__global__ __launch_bounds__(256, 6) void msl_main(
    const float* __restrict__ loc,
    const float* __restrict__ conf_d,
    const float* __restrict__ ploc,
    const float* __restrict__ pconf_d,
    const float* __restrict__ center,
    const float* __restrict__ priors,
    const float* __restrict__ targets,
    int K, int N, int nblk,
    float* __restrict__ out, int out_size)
{
    // dynamic shared: sp(2N) raw(2N) slab(N) rawlab(N) ebp(2N) | ans(2N+1 ints)
    extern __shared__ float sh[];
    float2* sp     = reinterpret_cast<float2*>(sh);        // width-sorted (t0*256,t1*256)
    float2* raw    = reinterpret_cast<float2*>(sh) + N;
    float*  slab   = sh + 4 * N;                           // width-sorted labels
    float*  rawlab = sh + 5 * N;
    float*  ebp    = sh + 6 * N;                           // 2N sorted endpoints
    int*    ans    = reinterpret_cast<int*>(sh + 8 * N);   // 2N+1 per-segment answers

    const int M = 2 * N;                                   // endpoint count
    const int b = blockIdx.y;
    const float* tg = targets + (size_t)b * N * 3;

    if (threadIdx.x < N) {
        int i = threadIdx.x;
        raw[i]    = make_float2(tg[i * 3 + 0] * 256.0f, tg[i * 3 + 1] * 256.0f);
        rawlab[i] = tg[i * 3 + 2];
    }
    __syncthreads();
    // stable rank-sort by width (ascending)
    if (threadIdx.x < N) {
        int i = threadIdx.x;
        float2 ti = raw[i];
        float  wi = ti.y - ti.x;
        int rank = 0;
        for (int j = 0; j < N; j++) {
            float2 tj = raw[j];
            float  wj = tj.y - tj.x;
            rank += (wj < wi) || (wj == wi && j < i);
        }
        sp[rank]   = ti;
        slab[rank] = rawlab[i];
    }
    // rank-sort the 2N endpoints (ascending, stable)
    if (threadIdx.x < M) {
        int i = threadIdx.x;
        float vi = (i < N) ? raw[i].x : raw[i - N].y;
        int rank = 0;
        for (int j = 0; j < M; j++) {
            float vj = (j < N) ? raw[j].x : raw[j - N].y;
            rank += (vj < vi) || (vj == vi && j < i);
        }
        ebp[rank] = vi;
    }
    __syncthreads();
    // per-segment answer: evaluate at segment representative (midpoint)
    for (int s = threadIdx.x; s <= M; s += blockDim.x) {
        float rep;
        if (s == 0)      rep = ebp[0] - 1.0f;
        else if (s == M) rep = ebp[M - 1] + 1.0f;
        else             rep = 0.5f * (ebp[s - 1] + ebp[s]);
        int a = -1;
        for (int n = 0; n < N; n++) {
            float2 t = sp[n];
            if (rep >= t.x && rep <= t.y) { a = n; break; }
        }
        ans[s] = a;
    }
    __syncthreads();

    const float EPS = 1.1920929e-7f;   // jnp.finfo(float32).eps
    float a0 = 0.f, a1 = 0.f, a2 = 0.f, a3 = 0.f, a4 = 0.f, a5 = 0.f, a6 = 0.f;
    const size_t base = (size_t)b * (size_t)K;
    const int stride = gridDim.x * blockDim.x;

    for (int k = blockIdx.x * blockDim.x + threadIdx.x; k < K; k += stride) {
        // hoisted loads (latency overlapped with the search)
        const float  c256 = priors[k] * 256.0f;
        const float2 pre  = __ldcs(reinterpret_cast<const float2*>(loc)     + base + k);
        const float2 pld  = __ldcs(reinterpret_cast<const float2*>(ploc)    + base + k);
        const float2 cd   = __ldcs(reinterpret_cast<const float2*>(conf_d)  + base + k);
        const float2 pcd  = __ldcs(reinterpret_cast<const float2*>(pconf_d) + base + k);
        const float  lg   = __ldcs(center + base + k);

        // branchless lower_bound: s = count(ebp < c256), segment (e[s-1], e[s]]
        int s = 0;
        #pragma unroll
        for (int step = 64; step >= 1; step >>= 1) {
            int ns = s + step;
            if (ns <= M && ebp[ns - 1] < c256) s = ns;
        }
        const int  ai    = ans[s];
        const bool found = (ai >= 0);
        const int  si    = found ? ai : 0;   // no-hit: contribution fully gated
        float2 tb  = sp[si];
        int confi  = found ? (int)slab[si] : 0;

        float ltl = c256 - tb.x;             // loc_t left
        float ltr = tb.y - c256;             // loc_t right
        float pl = pre.x, pr = pre.y;

        // iou(pre_loc, loc_t)
        float inter = fminf(pl, ltl) + fminf(pr, ltr);
        float uni   = pl + pr + ltl + ltr - inter;
        float iou   = __fdividef(inter, fmaxf(uni, EPS));
        int   pconfi = (iou < 0.5f) ? 0 : confi;
        float posf = (confi  > 0) ? 1.0f : 0.0f;
        float ppf  = (pconfi > 0) ? 1.0f : 0.0f;

        // GIoU loss
        float ac   = fmaxf(pl, ltl) + fmaxf(pr, ltr);
        float giou = iou - __fdividef(ac - uni, fmaxf(ac, EPS));
        a0 += (1.0f - giou) * posf;

        // prop-loc L1
        float hw  = 0.5f * (pl + pr);
        float rhw = __fdividef(1.0f, hw);          // hw >= 1 (loc in [1,51])
        float plt0 = (ltl - pl) * rhw;
        float plt1 = (ltr - pr) * rhw;
        a2 += (fabsf(pld.x - plt0) + fabsf(pld.y - plt1)) * ppf;

        // centerness BCE vs clipped iou of refined location
        float cl0 = hw * pld.x + pl;
        float cl1 = hw * pld.y + pr;
        float in2  = fminf(cl0, ltl) + fminf(cl1, ltr);
        float un2  = cl0 + cl1 + ltl + ltr - in2;
        float iou2 = fmaxf(__fdividef(in2, fmaxf(un2, EPS)), 0.0f);
        float bce  = fmaxf(lg, 0.0f) - lg * iou2 + __logf(1.0f + __expf(-fabsf(lg)));
        a4 += bce * posf;

        // focal(conf):  pt = softmax[target] = sigmoid(c_t - c_other)
        {
            float d  = (confi != 0) ? (cd.x - cd.y) : (cd.y - cd.x);
            float pt = __fdividef(1.0f, 1.0f + __expf(d)) + 1e-6f;
            float al = (confi != 0) ? 0.75f : 0.25f;
            float om = 1.0f - pt;
            a1 -= om * om * al * __logf(pt);
        }
        // focal(prop_conf)
        {
            float d  = (pconfi != 0) ? (pcd.x - pcd.y) : (pcd.y - pcd.x);
            float pt = __fdividef(1.0f, 1.0f + __expf(d)) + 1e-6f;
            float al = (pconfi != 0) ? 0.75f : 0.25f;
            float om = 1.0f - pt;
            a3 -= om * om * al * __logf(pt);
        }
        a5 += posf;
        a6 += ppf;
    }

    // warp reduction
    #pragma unroll
    for (int off = 16; off; off >>= 1) {
        a0 += __shfl_down_sync(0xffffffffu, a0, off);
        a1 += __shfl_down_sync(0xffffffffu, a1, off);
        a2 += __shfl_down_sync(0xffffffffu, a2, off);
        a3 += __shfl_down_sync(0xffffffffu, a3, off);
        a4 += __shfl_down_sync(0xffffffffu, a4, off);
        a5 += __shfl_down_sync(0xffffffffu, a5, off);
        a6 += __shfl_down_sync(0xffffffffu, a6, off);
    }
    __shared__ float red[8][8];
    int w  = threadIdx.x >> 5;
    int ln = threadIdx.x & 31;
    if (ln == 0) {
        red[w][0] = a0; red[w][1] = a1; red[w][2] = a2; red[w][3] = a3;
        red[w][4] = a4; red[w][5] = a5; red[w][6] = a6;
    }
    __syncthreads();
    const int blk = blockIdx.y * gridDim.x + blockIdx.x;
    if (threadIdx.x < 7) {
        float v = 0.0f;
        #pragma unroll
        for (int i = 0; i < 8; i++) v += red[i][threadIdx.x];
        g_part[blk * 8 + threadIdx.x] = v;   // deterministic per-block slot
    }
    __syncthreads();

    // ---- last-block finalize (deterministic fixed-order sum) ----
    __shared__ unsigned int s_ticket;
    if (threadIdx.x == 0) {
        __threadfence();
        s_ticket = atomicAdd(&g_count, 1u);
    }
    __syncthreads();
    if (s_ticket == (unsigned)(nblk - 1)) {
        __threadfence();
        __shared__ float tot[7];
        if (w < 7) {
            float v = 0.0f;
            for (int i = ln; i < nblk; i += 32) v += g_part[i * 8 + w];
            #pragma unroll
            for (int off = 16; off; off >>= 1) v += __shfl_down_sync(0xffffffffu, v, off);
            if (ln == 0) tot[w] = v;
        }
        __syncthreads();
        if (threadIdx.x == 0) {
            g_count = 0;                       // self-reset for graph replay
            float np = fmaxf(tot[5], 1.0f);
            float pn = fmaxf(tot[6], 1.0f);
            if (out_size > 0) out[0] = tot[0] / np;   // loss_l / Np
            if (out_size > 1) out[1] = tot[1] / np;   // loss_c / Np
            if (out_size > 2) out[2] = tot[2] / pn;   // loss_prop_l / PN
            if (out_size > 3) out[3] = tot[3] / pn;   // loss_prop_c / PN
            if (out_size > 4) out[4] = tot[4] / np;   // loss_ct / Np
        }
    }
}

extern "C" void kernel_launch(void* const* d_in, const int* in_sizes, int n_in,
                              void* d_out, int out_size)
{
    const float* loc     = (const float*)d_in[0];
    const float* conf    = (const float*)d_in[1];
    const float* ploc    = (const float*)d_in[2];
    const float* pconf   = (const float*)d_in[3];
    const float* center  = (const float*)d_in[4];
    const float* priors  = (const float*)d_in[5];
    const float* targets = (const float*)d_in[6];

    int K = in_sizes[5];                 // priors: (K,1)
    int B = in_sizes[4] / K;             // center: (B,K,1)
    int N = in_sizes[6] / (B * 3);       // targets: (B,N,3)

    int gx = 74;                          // 74*16 = 1184 blocks
    while ((long)gx * B > MAXPART && gx > 1) gx /= 2;
    int nblk = gx * B;

    dim3 grid(gx, B);
    size_t shmem = (size_t)(8 * N) * sizeof(float) + (size_t)(2 * N + 1) * sizeof(int);
    msl_main<<<grid, 256, shmem>>>(loc, conf, ploc, pconf, center, priors,
                                   targets, K, N, nblk, (float*)d_out, out_size);
}

// round 4
// speedup vs baseline: 2.5134x; 1.0973x over previous
#include <cuda_runtime.h>
#include <math_constants.h>

// ---------------------------------------------------------------------------
// MultiSegmentLoss fused kernel (single launch, single wave, LUT match).
// Match = first containing interval in width-sorted order (== argmin area).
// Piecewise-constant in prior center c: breakpoints = 2N interval endpoints.
// Per block we precompute a fused float4 segment table (t0,t1,label,·) and a
// 2048-bin u16 LUT over c in [0,256]; per prior the match is ~2 shared loads.
// ---------------------------------------------------------------------------

#define MAXPART 8192
#define LUTBITS 11
#define LUTSIZE (1 << LUTBITS)          // 2048 bins over [0,256] -> width 1/8

__device__ float        g_part[MAXPART * 8];
__device__ unsigned int g_count = 0;

__global__ __launch_bounds__(256, 6) void msl_main(
    const float* __restrict__ loc,
    const float* __restrict__ conf_d,
    const float* __restrict__ ploc,
    const float* __restrict__ pconf_d,
    const float* __restrict__ center,
    const float* __restrict__ priors,
    const float* __restrict__ targets,
    int K, int N, int nblk,
    float* __restrict__ out, int out_size)
{
    extern __shared__ float sh[];
    const int M = 2 * N;
    // layout: seg float4[M+1] | sp float2[N] | raw float2[N] | slab[N] | rawlab[N]
    //         | ebp[M+1] | lut u16[LUTSIZE]
    float4* seg    = reinterpret_cast<float4*>(sh);
    float2* sp     = reinterpret_cast<float2*>(seg + (M + 1));
    float2* raw    = sp + N;
    float*  slab   = reinterpret_cast<float*>(raw + N);
    float*  rawlab = slab + N;
    float*  ebp    = rawlab + N;                       // M+1 (padded +INF)
    unsigned short* lut = reinterpret_cast<unsigned short*>(ebp + (M + 1));

    const int b = blockIdx.y;
    const float* tg = targets + (size_t)b * N * 3;

    if (threadIdx.x < N) {
        int i = threadIdx.x;
        raw[i]    = make_float2(tg[i * 3 + 0] * 256.0f, tg[i * 3 + 1] * 256.0f);
        rawlab[i] = tg[i * 3 + 2];
    }
    __syncthreads();
    // stable rank-sort by width (ascending)
    if (threadIdx.x < N) {
        int i = threadIdx.x;
        float2 ti = raw[i];
        float  wi = ti.y - ti.x;
        int rank = 0;
        for (int j = 0; j < N; j++) {
            float2 tj = raw[j];
            float  wj = tj.y - tj.x;
            rank += (wj < wi) || (wj == wi && j < i);
        }
        sp[rank]   = ti;
        slab[rank] = rawlab[i];
    }
    // stable rank-sort of the 2N endpoints
    if (threadIdx.x < M) {
        int i = threadIdx.x;
        float vi = (i < N) ? raw[i].x : raw[i - N].y;
        int rank = 0;
        for (int j = 0; j < M; j++) {
            float vj = (j < N) ? raw[j].x : raw[j - N].y;
            rank += (vj < vi) || (vj == vi && j < i);
        }
        ebp[rank] = vi;
    }
    if (threadIdx.x == M) ebp[M] = CUDART_INF_F;       // sentinel
    __syncthreads();
    // fused per-segment answer table: (t0, t1, label-or-0, unused)
    for (int s = threadIdx.x; s <= M; s += blockDim.x) {
        float rep;
        if (s == 0)      rep = ebp[0] - 1.0f;
        else if (s == M) rep = ebp[M - 1] + 1.0f;
        else             rep = 0.5f * (ebp[s - 1] + ebp[s]);
        float t0 = 0.f, t1 = 0.f, lb = 0.f;
        for (int n = 0; n < N; n++) {
            float2 t = sp[n];
            if (rep >= t.x && rep <= t.y) { t0 = t.x; t1 = t.y; lb = slab[n]; break; }
        }
        seg[s] = make_float4(t0, t1, lb, 0.f);
    }
    // LUT: lut[bin] = count(ebp < bin/8)  (7-step binary search over M)
    for (int bin = threadIdx.x; bin < LUTSIZE; bin += blockDim.x) {
        float edge = (float)bin * (256.0f / LUTSIZE);
        int s = 0;
        #pragma unroll
        for (int step = 64; step >= 1; step >>= 1) {
            int ns = s + step;
            if (ns <= M && ebp[ns - 1] < edge) s = ns;
        }
        lut[bin] = (unsigned short)s;
    }
    __syncthreads();

    const float EPS = 1.1920929e-7f;   // jnp.finfo(float32).eps
    float a0 = 0.f, a1 = 0.f, a2 = 0.f, a3 = 0.f, a4 = 0.f, a5 = 0.f, a6 = 0.f;
    const size_t base = (size_t)b * (size_t)K;
    const int stride = gridDim.x * blockDim.x;

    for (int k = blockIdx.x * blockDim.x + threadIdx.x; k < K; k += stride) {
        const float  c256 = priors[k] * 256.0f;
        const float2 pre  = __ldcs(reinterpret_cast<const float2*>(loc)     + base + k);
        const float2 pld  = __ldcs(reinterpret_cast<const float2*>(ploc)    + base + k);
        const float2 cd   = __ldcs(reinterpret_cast<const float2*>(conf_d)  + base + k);
        const float2 pcd  = __ldcs(reinterpret_cast<const float2*>(pconf_d) + base + k);
        const float  lg   = __ldcs(center + base + k);

        // LUT + forward fixup: s = count(ebp < c256)
        int bin = (int)(c256 * (LUTSIZE / 256.0f));
        bin = min(max(bin, 0), LUTSIZE - 1);
        int s = lut[bin];
        while (ebp[s] < c256) s++;                 // ~1 probe (sentinel-bounded)
        const float4 sg = seg[s];

        const bool pos = (sg.z > 0.0f);
        float ltl = c256 - sg.x;                   // loc_t left (gated if !pos)
        float ltr = sg.y - c256;
        float pl = pre.x, pr = pre.y;

        // iou(pre_loc, loc_t)
        float inter = fminf(pl, ltl) + fminf(pr, ltr);
        float uni   = pl + pr + ltl + ltr - inter;
        float iou   = __fdividef(inter, fmaxf(uni, EPS));
        const bool ppos = pos && (iou >= 0.5f);
        float posf = pos  ? 1.0f : 0.0f;
        float ppf  = ppos ? 1.0f : 0.0f;

        // GIoU loss
        float ac   = fmaxf(pl, ltl) + fmaxf(pr, ltr);
        float giou = iou - __fdividef(ac - uni, fmaxf(ac, EPS));
        a0 += (1.0f - giou) * posf;

        // prop-loc L1
        float hw  = 0.5f * (pl + pr);
        float rhw = __fdividef(1.0f, hw);
        float plt0 = (ltl - pl) * rhw;
        float plt1 = (ltr - pr) * rhw;
        a2 += (fabsf(pld.x - plt0) + fabsf(pld.y - plt1)) * ppf;

        // centerness BCE vs clipped iou of refined location
        float cl0 = hw * pld.x + pl;
        float cl1 = hw * pld.y + pr;
        float in2  = fminf(cl0, ltl) + fminf(cl1, ltr);
        float un2  = cl0 + cl1 + ltl + ltr - in2;
        float iou2 = fmaxf(__fdividef(in2, fmaxf(un2, EPS)), 0.0f);
        float bce  = fmaxf(lg, 0.0f) - lg * iou2 + __logf(1.0f + __expf(-fabsf(lg)));
        a4 += bce * posf;

        // focal(conf): pt = softmax[target] = sigmoid(target_logit - other)
        {
            float dd = cd.x - cd.y;
            float d  = pos ? dd : -dd;
            float pt = __fdividef(1.0f, 1.0f + __expf(d)) + 1e-6f;
            float al = pos ? 0.75f : 0.25f;
            float om = 1.0f - pt;
            a1 -= om * om * al * __logf(pt);
        }
        // focal(prop_conf)
        {
            float dd = pcd.x - pcd.y;
            float d  = ppos ? dd : -dd;
            float pt = __fdividef(1.0f, 1.0f + __expf(d)) + 1e-6f;
            float al = ppos ? 0.75f : 0.25f;
            float om = 1.0f - pt;
            a3 -= om * om * al * __logf(pt);
        }
        a5 += posf;
        a6 += ppf;
    }

    // warp reduction
    #pragma unroll
    for (int off = 16; off; off >>= 1) {
        a0 += __shfl_down_sync(0xffffffffu, a0, off);
        a1 += __shfl_down_sync(0xffffffffu, a1, off);
        a2 += __shfl_down_sync(0xffffffffu, a2, off);
        a3 += __shfl_down_sync(0xffffffffu, a3, off);
        a4 += __shfl_down_sync(0xffffffffu, a4, off);
        a5 += __shfl_down_sync(0xffffffffu, a5, off);
        a6 += __shfl_down_sync(0xffffffffu, a6, off);
    }
    __shared__ float red[8][8];
    int w  = threadIdx.x >> 5;
    int ln = threadIdx.x & 31;
    if (ln == 0) {
        red[w][0] = a0; red[w][1] = a1; red[w][2] = a2; red[w][3] = a3;
        red[w][4] = a4; red[w][5] = a5; red[w][6] = a6;
    }
    __syncthreads();
    const int blk = blockIdx.y * gridDim.x + blockIdx.x;
    if (threadIdx.x < 7) {
        float v = 0.0f;
        #pragma unroll
        for (int i = 0; i < 8; i++) v += red[i][threadIdx.x];
        g_part[blk * 8 + threadIdx.x] = v;   // deterministic per-block slot
    }
    __syncthreads();

    // ---- last-block finalize (deterministic fixed-order sum) ----
    __shared__ unsigned int s_ticket;
    if (threadIdx.x == 0) {
        __threadfence();
        s_ticket = atomicAdd(&g_count, 1u);
    }
    __syncthreads();
    if (s_ticket == (unsigned)(nblk - 1)) {
        __threadfence();
        __shared__ float tot[7];
        if (w < 7) {
            float v = 0.0f;
            for (int i = ln; i < nblk; i += 32) v += g_part[i * 8 + w];
            #pragma unroll
            for (int off = 16; off; off >>= 1) v += __shfl_down_sync(0xffffffffu, v, off);
            if (ln == 0) tot[w] = v;
        }
        __syncthreads();
        if (threadIdx.x == 0) {
            g_count = 0;                       // self-reset for graph replay
            float np = fmaxf(tot[5], 1.0f);
            float pn = fmaxf(tot[6], 1.0f);
            if (out_size > 0) out[0] = tot[0] / np;   // loss_l / Np
            if (out_size > 1) out[1] = tot[1] / np;   // loss_c / Np
            if (out_size > 2) out[2] = tot[2] / pn;   // loss_prop_l / PN
            if (out_size > 3) out[3] = tot[3] / pn;   // loss_prop_c / PN
            if (out_size > 4) out[4] = tot[4] / np;   // loss_ct / Np
        }
    }
}

extern "C" void kernel_launch(void* const* d_in, const int* in_sizes, int n_in,
                              void* d_out, int out_size)
{
    const float* loc     = (const float*)d_in[0];
    const float* conf    = (const float*)d_in[1];
    const float* ploc    = (const float*)d_in[2];
    const float* pconf   = (const float*)d_in[3];
    const float* center  = (const float*)d_in[4];
    const float* priors  = (const float*)d_in[5];
    const float* targets = (const float*)d_in[6];

    int K = in_sizes[5];                 // priors: (K,1)
    int B = in_sizes[4] / K;             // center: (B,K,1)
    int N = in_sizes[6] / (B * 3);       // targets: (B,N,3)
    int M = 2 * N;

    // Single wave: 6 resident blocks/SM * 148 SMs = 888 slots.
    int gx = 888 / (B > 0 ? B : 1);
    if (gx < 1) gx = 1;
    while ((long)gx * B > MAXPART && gx > 1) gx /= 2;
    int nblk = gx * B;

    dim3 grid(gx, B);
    size_t shmem = (size_t)(M + 1) * 16        // seg float4
                 + (size_t)N * 8 * 2           // sp + raw float2
                 + (size_t)N * 4 * 2           // slab + rawlab
                 + (size_t)(M + 1) * 4         // ebp (+sentinel)
                 + (size_t)LUTSIZE * 2;        // u16 lut
    msl_main<<<grid, 256, shmem>>>(loc, conf, ploc, pconf, center, priors,
                                   targets, K, N, nblk, (float*)d_out, out_size);
}

// round 5
// speedup vs baseline: 2.9710x; 1.1821x over previous
#include <cuda_runtime.h>
#include <math_constants.h>

// ---------------------------------------------------------------------------
// MultiSegmentLoss fused kernel — single launch, single wave, x2 elements per
// thread (float4 loads), O(1) LUT match.
// Match = first containing interval in width-sorted order (== argmin area),
// piecewise-constant in prior center c; per-block: fused float4 segment table
// + 2048-bin u16 LUT over c in [0,256].
// ---------------------------------------------------------------------------

#define MAXPART 8192
#define LUTSIZE 2048                    // bins over [0,256] -> width 1/8

__device__ float        g_part[MAXPART * 8];
__device__ unsigned int g_count = 0;

struct Accum { float a0, a1, a2, a3, a4, a5, a6; };

__device__ __forceinline__ void process_elem(
    float c256, float pl, float pr, float cdx, float cdy,
    float pldx, float pldy, float pcdx, float pcdy, float lg,
    const float* __restrict__ ebp, const float4* __restrict__ seg,
    const unsigned short* __restrict__ lut, Accum& A)
{
    const float EPS = 1.1920929e-7f;   // jnp.finfo(float32).eps

    int bin = (int)(c256 * (LUTSIZE / 256.0f));
    bin = min(max(bin, 0), LUTSIZE - 1);
    int s = lut[bin];
    s += (ebp[s] < c256);
    s += (ebp[s] < c256);
    while (ebp[s] < c256) s++;          // ~never taken (INF sentinel bounds it)
    const float4 sg = seg[s];

    const bool pos = (sg.z > 0.0f);
    float ltl = c256 - sg.x;            // loc_t left (fully gated if !pos)
    float ltr = sg.y - c256;

    // iou(pre_loc, loc_t)
    float inter = fminf(pl, ltl) + fminf(pr, ltr);
    float uni   = pl + pr + ltl + ltr - inter;
    float iou   = __fdividef(inter, fmaxf(uni, EPS));
    const bool ppos = pos && (iou >= 0.5f);
    float posf = pos  ? 1.0f : 0.0f;
    float ppf  = ppos ? 1.0f : 0.0f;

    // GIoU loss
    float ac   = fmaxf(pl, ltl) + fmaxf(pr, ltr);
    float giou = iou - __fdividef(ac - uni, fmaxf(ac, EPS));
    A.a0 += (1.0f - giou) * posf;

    // prop-loc L1
    float hw  = 0.5f * (pl + pr);
    float rhw = __fdividef(1.0f, hw);
    float plt0 = (ltl - pl) * rhw;
    float plt1 = (ltr - pr) * rhw;
    A.a2 += (fabsf(pldx - plt0) + fabsf(pldy - plt1)) * ppf;

    // centerness BCE vs clipped iou of refined location
    float cl0 = hw * pldx + pl;
    float cl1 = hw * pldy + pr;
    float in2  = fminf(cl0, ltl) + fminf(cl1, ltr);
    float un2  = cl0 + cl1 + ltl + ltr - in2;
    float iou2 = fmaxf(__fdividef(in2, fmaxf(un2, EPS)), 0.0f);
    float bce  = fmaxf(lg, 0.0f) - lg * iou2 + __logf(1.0f + __expf(-fabsf(lg)));
    A.a4 += bce * posf;

    // focal(conf): pt = softmax[target] = sigmoid(target - other)
    {
        float dd = cdx - cdy;
        float d  = pos ? dd : -dd;
        float pt = __fdividef(1.0f, 1.0f + __expf(d)) + 1e-6f;
        float al = pos ? 0.75f : 0.25f;
        float om = 1.0f - pt;
        A.a1 -= om * om * al * __logf(pt);
    }
    // focal(prop_conf)
    {
        float dd = pcdx - pcdy;
        float d  = ppos ? dd : -dd;
        float pt = __fdividef(1.0f, 1.0f + __expf(d)) + 1e-6f;
        float al = ppos ? 0.75f : 0.25f;
        float om = 1.0f - pt;
        A.a3 -= om * om * al * __logf(pt);
    }
    A.a5 += posf;
    A.a6 += ppf;
}

__global__ __launch_bounds__(256, 4) void msl_main(
    const float* __restrict__ loc,
    const float* __restrict__ conf_d,
    const float* __restrict__ ploc,
    const float* __restrict__ pconf_d,
    const float* __restrict__ center,
    const float* __restrict__ priors,
    const float* __restrict__ targets,
    int K, int N, int nblk,
    float* __restrict__ out, int out_size)
{
    extern __shared__ float sh[];
    const int M = 2 * N;
    float4* seg    = reinterpret_cast<float4*>(sh);               // M+1
    float2* sp     = reinterpret_cast<float2*>(seg + (M + 1));    // N
    float2* raw    = sp + N;                                      // N
    float*  slab   = reinterpret_cast<float*>(raw + N);           // N
    float*  rawlab = slab + N;                                    // N
    float*  ebp    = rawlab + N;                                  // M+1 (INF pad)
    unsigned short* lut = reinterpret_cast<unsigned short*>(ebp + (M + 1));

    const int b = blockIdx.y;
    const float* tg = targets + (size_t)b * N * 3;

    if (threadIdx.x < N) {
        int i = threadIdx.x;
        raw[i]    = make_float2(tg[i * 3 + 0] * 256.0f, tg[i * 3 + 1] * 256.0f);
        rawlab[i] = tg[i * 3 + 2];
    }
    __syncthreads();
    if (threadIdx.x < N) {                          // stable width rank-sort
        int i = threadIdx.x;
        float2 ti = raw[i];
        float  wi = ti.y - ti.x;
        int rank = 0;
        for (int j = 0; j < N; j++) {
            float2 tj = raw[j];
            float  wj = tj.y - tj.x;
            rank += (wj < wi) || (wj == wi && j < i);
        }
        sp[rank]   = ti;
        slab[rank] = rawlab[i];
    }
    if (threadIdx.x < M) {                          // stable endpoint rank-sort
        int i = threadIdx.x;
        float vi = (i < N) ? raw[i].x : raw[i - N].y;
        int rank = 0;
        for (int j = 0; j < M; j++) {
            float vj = (j < N) ? raw[j].x : raw[j - N].y;
            rank += (vj < vi) || (vj == vi && j < i);
        }
        ebp[rank] = vi;
    }
    if (threadIdx.x == M) ebp[M] = CUDART_INF_F;
    __syncthreads();
    for (int s = threadIdx.x; s <= M; s += blockDim.x) {   // segment table
        float rep;
        if (s == 0)      rep = ebp[0] - 1.0f;
        else if (s == M) rep = ebp[M - 1] + 1.0f;
        else             rep = 0.5f * (ebp[s - 1] + ebp[s]);
        float t0 = 0.f, t1 = 0.f, lb = 0.f;
        for (int n = 0; n < N; n++) {
            float2 t = sp[n];
            if (rep >= t.x && rep <= t.y) { t0 = t.x; t1 = t.y; lb = slab[n]; break; }
        }
        seg[s] = make_float4(t0, t1, lb, 0.f);
    }
    for (int bin = threadIdx.x; bin < LUTSIZE; bin += blockDim.x) {
        float edge = (float)bin * (256.0f / LUTSIZE);
        int s = 0;
        #pragma unroll
        for (int step = 64; step >= 1; step >>= 1) {
            int ns = s + step;
            if (ns <= M && ebp[ns - 1] < edge) s = ns;
        }
        lut[bin] = (unsigned short)s;
    }
    __syncthreads();

    Accum A = {0.f, 0.f, 0.f, 0.f, 0.f, 0.f, 0.f};
    const int Kh = K >> 1;                      // pairs
    const size_t baseh = (size_t)b * (size_t)Kh;  // float4/float2-pair units

    const float4* loc4  = reinterpret_cast<const float4*>(loc)     + baseh;
    const float4* cd4   = reinterpret_cast<const float4*>(conf_d)  + baseh;
    const float4* pld4  = reinterpret_cast<const float4*>(ploc)    + baseh;
    const float4* pcd4  = reinterpret_cast<const float4*>(pconf_d) + baseh;
    const float2* ctr2  = reinterpret_cast<const float2*>(center)  + baseh;
    const float2* pri2  = reinterpret_cast<const float2*>(priors);

    const int stride = gridDim.x * blockDim.x;
    for (int p = blockIdx.x * blockDim.x + threadIdx.x; p < Kh; p += stride) {
        const float2 pc  = pri2[p];
        const float4 pre = __ldcs(loc4  + p);
        const float4 pld = __ldcs(pld4  + p);
        const float4 cd  = __ldcs(cd4   + p);
        const float4 pcd = __ldcs(pcd4  + p);
        const float2 lg  = __ldcs(ctr2  + p);

        process_elem(pc.x * 256.0f, pre.x, pre.y, cd.x, cd.y,
                     pld.x, pld.y, pcd.x, pcd.y, lg.x, ebp, seg, lut, A);
        process_elem(pc.y * 256.0f, pre.z, pre.w, cd.z, cd.w,
                     pld.z, pld.w, pcd.z, pcd.w, lg.y, ebp, seg, lut, A);
    }
    // odd-K tail (not hit for K=200000; handled for safety)
    if ((K & 1) && blockIdx.x == 0 && threadIdx.x == 0) {
        int k = K - 1;
        const size_t base = (size_t)b * (size_t)K;
        float2 pre = reinterpret_cast<const float2*>(loc)[base + k];
        float2 pld = reinterpret_cast<const float2*>(ploc)[base + k];
        float2 cd  = reinterpret_cast<const float2*>(conf_d)[base + k];
        float2 pcd = reinterpret_cast<const float2*>(pconf_d)[base + k];
        process_elem(priors[k] * 256.0f, pre.x, pre.y, cd.x, cd.y,
                     pld.x, pld.y, pcd.x, pcd.y, center[base + k],
                     ebp, seg, lut, A);
    }

    // warp reduction
    #pragma unroll
    for (int off = 16; off; off >>= 1) {
        A.a0 += __shfl_down_sync(0xffffffffu, A.a0, off);
        A.a1 += __shfl_down_sync(0xffffffffu, A.a1, off);
        A.a2 += __shfl_down_sync(0xffffffffu, A.a2, off);
        A.a3 += __shfl_down_sync(0xffffffffu, A.a3, off);
        A.a4 += __shfl_down_sync(0xffffffffu, A.a4, off);
        A.a5 += __shfl_down_sync(0xffffffffu, A.a5, off);
        A.a6 += __shfl_down_sync(0xffffffffu, A.a6, off);
    }
    __shared__ float red[8][8];
    int w  = threadIdx.x >> 5;
    int ln = threadIdx.x & 31;
    if (ln == 0) {
        red[w][0] = A.a0; red[w][1] = A.a1; red[w][2] = A.a2; red[w][3] = A.a3;
        red[w][4] = A.a4; red[w][5] = A.a5; red[w][6] = A.a6;
    }
    __syncthreads();
    const int blk = blockIdx.y * gridDim.x + blockIdx.x;
    if (threadIdx.x < 7) {
        float v = 0.0f;
        #pragma unroll
        for (int i = 0; i < 8; i++) v += red[i][threadIdx.x];
        g_part[blk * 8 + threadIdx.x] = v;   // deterministic per-block slot
    }
    __syncthreads();

    // ---- last-block finalize (deterministic fixed-order sum) ----
    __shared__ unsigned int s_ticket;
    if (threadIdx.x == 0) {
        __threadfence();
        s_ticket = atomicAdd(&g_count, 1u);
    }
    __syncthreads();
    if (s_ticket == (unsigned)(nblk - 1)) {
        __threadfence();
        __shared__ float tot[7];
        if (w < 7) {
            float v = 0.0f;
            for (int i = ln; i < nblk; i += 32) v += g_part[i * 8 + w];
            #pragma unroll
            for (int off = 16; off; off >>= 1) v += __shfl_down_sync(0xffffffffu, v, off);
            if (ln == 0) tot[w] = v;
        }
        __syncthreads();
        if (threadIdx.x == 0) {
            g_count = 0;                       // self-reset for graph replay
            float np = fmaxf(tot[5], 1.0f);
            float pn = fmaxf(tot[6], 1.0f);
            if (out_size > 0) out[0] = tot[0] / np;   // loss_l / Np
            if (out_size > 1) out[1] = tot[1] / np;   // loss_c / Np
            if (out_size > 2) out[2] = tot[2] / pn;   // loss_prop_l / PN
            if (out_size > 3) out[3] = tot[3] / pn;   // loss_prop_c / PN
            if (out_size > 4) out[4] = tot[4] / np;   // loss_ct / Np
        }
    }
}

extern "C" void kernel_launch(void* const* d_in, const int* in_sizes, int n_in,
                              void* d_out, int out_size)
{
    const float* loc     = (const float*)d_in[0];
    const float* conf    = (const float*)d_in[1];
    const float* ploc    = (const float*)d_in[2];
    const float* pconf   = (const float*)d_in[3];
    const float* center  = (const float*)d_in[4];
    const float* priors  = (const float*)d_in[5];
    const float* targets = (const float*)d_in[6];

    int K = in_sizes[5];                 // priors: (K,1)
    int B = in_sizes[4] / K;             // center: (B,K,1)
    int N = in_sizes[6] / (B * 3);       // targets: (B,N,3)
    int M = 2 * N;

    // Single wave at 4 blocks/SM: 4 * 148 = 592 slots.
    int gx = 592 / (B > 0 ? B : 1);
    if (gx < 1) gx = 1;
    while ((long)gx * B > MAXPART && gx > 1) gx /= 2;
    int nblk = gx * B;

    dim3 grid(gx, B);
    size_t shmem = (size_t)(M + 1) * 16        // seg float4
                 + (size_t)N * 8 * 2           // sp + raw float2
                 + (size_t)N * 4 * 2           // slab + rawlab
                 + (size_t)(M + 1) * 4         // ebp (+sentinel)
                 + (size_t)LUTSIZE * 2;        // u16 lut
    msl_main<<<grid, 256, shmem>>>(loc, conf, ploc, pconf, center, priors,
                                   targets, K, N, nblk, (float*)d_out, out_size);
}